// round 1
// baseline (speedup 1.0000x reference)
#include <cuda_runtime.h>

// Problem constants
static constexpr int B  = 2;
static constexpr int S  = 2048;
static constexpr int D  = 1024;
static constexpr int H  = 16;
static constexpr int DK = 64;
static constexpr int M  = B * S;   // 4096 rows for the projection GEMMs

// Scratch (device globals — no allocation allowed in kernel_launch)
__device__ float g_q[(size_t)B * H * S * DK];    // [B,H,S,DK]
__device__ float g_k[(size_t)B * H * S * DK];
__device__ float g_v[(size_t)B * H * S * DK];
__device__ float g_attn[(size_t)B * S * D];      // [B,S,D]

// ---------------------------------------------------------------------------
// SGEMM 128x128x8, 256 threads, 8x8 microtile (split 4+4 at +64 offsets)
// A: [rows, D] row-major, W: [D, N=D] row-major
// ---------------------------------------------------------------------------
static constexpr int BM = 128, BN = 128, BK = 8;

__device__ __forceinline__ void sgemm_body(const float* __restrict__ A,
                                           const float* __restrict__ W,
                                           float (&acc)[8][8])
{
    __shared__ float As[BK][BM];
    __shared__ float Bs[BK][BN];

    const int tid = threadIdx.x;
    const int bm = blockIdx.y * BM;
    const int bn = blockIdx.x * BN;
    const int ar = tid >> 1, ac = (tid & 1) * 4;   // A tile: 128 rows x 2 float4
    const int br = tid >> 5, bc = (tid & 31) * 4;  // B tile: 8 rows x 32 float4
    const int ty = tid >> 4, tx = tid & 15;

    #pragma unroll
    for (int i = 0; i < 8; i++)
        #pragma unroll
        for (int j = 0; j < 8; j++) acc[i][j] = 0.f;

    const float* Aptr = A + (size_t)(bm + ar) * D + ac;
    const float* Wptr = W + (size_t)br * D + bn + bc;

    for (int kk = 0; kk < D; kk += BK) {
        float4 av = *(const float4*)(Aptr + kk);
        float4 bv = *(const float4*)(Wptr + (size_t)kk * D);
        __syncthreads();   // previous compute done before overwrite
        As[ac + 0][ar] = av.x;
        As[ac + 1][ar] = av.y;
        As[ac + 2][ar] = av.z;
        As[ac + 3][ar] = av.w;
        *(float4*)&Bs[br][bc] = bv;
        __syncthreads();
        #pragma unroll
        for (int k = 0; k < BK; k++) {
            float a[8], b[8];
            *(float4*)&a[0] = *(const float4*)&As[k][ty * 4];
            *(float4*)&a[4] = *(const float4*)&As[k][64 + ty * 4];
            *(float4*)&b[0] = *(const float4*)&Bs[k][tx * 4];
            *(float4*)&b[4] = *(const float4*)&Bs[k][64 + tx * 4];
            #pragma unroll
            for (int i = 0; i < 8; i++)
                #pragma unroll
                for (int j = 0; j < 8; j++)
                    acc[i][j] += a[i] * b[j];
        }
    }
}

// Fused Q/K/V projections. blockIdx.z selects which projection.
// Output written in [B,H,S,DK] layout for the attention kernel.
__global__ __launch_bounds__(256) void qkv_proj_kernel(
    const float* __restrict__ Qin, const float* __restrict__ Kin,
    const float* __restrict__ Vin,
    const float* __restrict__ Wq, const float* __restrict__ Wk,
    const float* __restrict__ Wv)
{
    const int z = blockIdx.z;
    const float* A = (z == 0) ? Qin : (z == 1) ? Kin : Vin;
    const float* W = (z == 0) ? Wq  : (z == 1) ? Wk  : Wv;
    float* dst     = (z == 0) ? g_q : (z == 1) ? g_k : g_v;

    float acc[8][8];
    sgemm_body(A, W, acc);

    const int tid = threadIdx.x;
    const int ty = tid >> 4, tx = tid & 15;
    const int bm = blockIdx.y * BM, bn = blockIdx.x * BN;

    #pragma unroll
    for (int i = 0; i < 8; i++) {
        int m = bm + ((i < 4) ? (ty * 4 + i) : (64 + ty * 4 + i - 4));
        int b = m >> 11;           // /S
        int s = m & (S - 1);
        #pragma unroll
        for (int j = 0; j < 8; j++) {
            int n = bn + ((j < 4) ? (tx * 4 + j) : (64 + tx * 4 + j - 4));
            int h = n >> 6;        // /DK
            int d = n & (DK - 1);
            dst[((size_t)(b * H + h) * S + s) * DK + d] = acc[i][j];
        }
    }
}

// Output projection: g_attn [4096,1024] @ Wo [1024,1024] + bo
__global__ __launch_bounds__(256) void out_proj_kernel(
    const float* __restrict__ Wo, const float* __restrict__ bo,
    float* __restrict__ out)
{
    float acc[8][8];
    sgemm_body(g_attn, Wo, acc);

    const int tid = threadIdx.x;
    const int ty = tid >> 4, tx = tid & 15;
    const int bm = blockIdx.y * BM, bn = blockIdx.x * BN;

    #pragma unroll
    for (int i = 0; i < 8; i++) {
        int m = bm + ((i < 4) ? (ty * 4 + i) : (64 + ty * 4 + i - 4));
        #pragma unroll
        for (int j = 0; j < 8; j++) {
            int n = bn + ((j < 4) ? (tx * 4 + j) : (64 + tx * 4 + j - 4));
            out[(size_t)m * D + n] = acc[i][j] + bo[n];
        }
    }
}

// ---------------------------------------------------------------------------
// Flash attention, fp32. One CTA per (qtile of 64 rows, b*h).
// 256 threads = 16x16, each thread owns a 4x4 microtile of the 64x64 score
// tile and a 4x4 microtile of the 64(rows)x64(dk) output accumulator.
// Shared: Qs[64][65], KVs[64][65] (K then reused for V), Ps[64][65].
// ---------------------------------------------------------------------------
static constexpr int PAD = 65;
static constexpr int ATTN_SMEM = 3 * 64 * PAD * (int)sizeof(float);  // 49920 B

__global__ __launch_bounds__(256) void flash_attn_kernel()
{
    extern __shared__ float sm[];
    float* Qs  = sm;
    float* KVs = sm + 64 * PAD;
    float* Ps  = sm + 2 * 64 * PAD;

    const int tid = threadIdx.x;
    const int ty = tid >> 4, tx = tid & 15;
    // Reverse order: longest (most causal work) q-tiles launch first.
    const int qtile = (int)gridDim.x - 1 - (int)blockIdx.x;
    const int bh = blockIdx.y;

    const float* qp = g_q + (size_t)bh * S * DK + (size_t)qtile * 64 * DK;
    const float* kp = g_k + (size_t)bh * S * DK;
    const float* vp = g_v + (size_t)bh * S * DK;

    // Load Q tile (64 x 64), coalesced float4, scalar stores into padded smem.
    #pragma unroll
    for (int i = 0; i < 4; i++) {
        int f = tid + 256 * i;
        int r = f >> 4, c = (f & 15) * 4;
        float4 v4 = *(const float4*)(qp + r * DK + c);
        Qs[r * PAD + c + 0] = v4.x;
        Qs[r * PAD + c + 1] = v4.y;
        Qs[r * PAD + c + 2] = v4.z;
        Qs[r * PAD + c + 3] = v4.w;
    }

    float row_m[4], row_l[4], acc[4][4];
    #pragma unroll
    for (int i = 0; i < 4; i++) {
        row_m[i] = -1e30f;
        row_l[i] = 0.f;
        #pragma unroll
        for (int j = 0; j < 4; j++) acc[i][j] = 0.f;
    }
    __syncthreads();

    for (int nt = 0; nt <= qtile; nt++) {
        // --- stage K tile ---
        const float* kt = kp + (size_t)nt * 64 * DK;
        float4 kreg[4];
        #pragma unroll
        for (int i = 0; i < 4; i++) {
            int f = tid + 256 * i;
            kreg[i] = *(const float4*)(kt + (f >> 4) * DK + (f & 15) * 4);
        }
        __syncthreads();  // previous iteration's PV reads done
        #pragma unroll
        for (int i = 0; i < 4; i++) {
            int f = tid + 256 * i;
            int r = f >> 4, c = (f & 15) * 4;
            KVs[r * PAD + c + 0] = kreg[i].x;
            KVs[r * PAD + c + 1] = kreg[i].y;
            KVs[r * PAD + c + 2] = kreg[i].z;
            KVs[r * PAD + c + 3] = kreg[i].w;
        }
        __syncthreads();

        // --- S = Q K^T (64x64x64) ---
        float sv[4][4];
        #pragma unroll
        for (int i = 0; i < 4; i++)
            #pragma unroll
            for (int j = 0; j < 4; j++) sv[i][j] = 0.f;

        #pragma unroll 16
        for (int d = 0; d < DK; d++) {
            float qv[4], kv[4];
            #pragma unroll
            for (int i = 0; i < 4; i++) qv[i] = Qs[(ty * 4 + i) * PAD + d];
            #pragma unroll
            for (int j = 0; j < 4; j++) kv[j] = KVs[(tx * 4 + j) * PAD + d];
            #pragma unroll
            for (int i = 0; i < 4; i++)
                #pragma unroll
                for (int j = 0; j < 4; j++)
                    sv[i][j] += qv[i] * kv[j];
        }

        const bool diag = (nt == qtile);
        #pragma unroll
        for (int i = 0; i < 4; i++)
            #pragma unroll
            for (int j = 0; j < 4; j++) {
                float x = sv[i][j] * 0.125f;  // 1/sqrt(64)
                if (diag && (tx * 4 + j) > (ty * 4 + i)) x = -1e30f;
                sv[i][j] = x;
            }

        // --- online softmax (row stats reduced over the 16-lane tx group) ---
        #pragma unroll
        for (int i = 0; i < 4; i++) {
            float mx = fmaxf(fmaxf(sv[i][0], sv[i][1]), fmaxf(sv[i][2], sv[i][3]));
            #pragma unroll
            for (int off = 8; off >= 1; off >>= 1)
                mx = fmaxf(mx, __shfl_xor_sync(0xffffffffu, mx, off, 16));
            float m_new = fmaxf(row_m[i], mx);
            float sc = __expf(row_m[i] - m_new);
            float sum = 0.f;
            #pragma unroll
            for (int j = 0; j < 4; j++) {
                float p = __expf(sv[i][j] - m_new);
                Ps[(ty * 4 + i) * PAD + tx * 4 + j] = p;
                sum += p;
            }
            #pragma unroll
            for (int off = 8; off >= 1; off >>= 1)
                sum += __shfl_xor_sync(0xffffffffu, sum, off, 16);
            row_l[i] = row_l[i] * sc + sum;
            row_m[i] = m_new;
            #pragma unroll
            for (int j = 0; j < 4; j++) acc[i][j] *= sc;
        }

        // --- stage V tile over K's smem buffer ---
        const float* vt = vp + (size_t)nt * 64 * DK;
        float4 vreg[4];
        #pragma unroll
        for (int i = 0; i < 4; i++) {
            int f = tid + 256 * i;
            vreg[i] = *(const float4*)(vt + (f >> 4) * DK + (f & 15) * 4);
        }
        __syncthreads();  // all K reads + P writes complete
        #pragma unroll
        for (int i = 0; i < 4; i++) {
            int f = tid + 256 * i;
            int r = f >> 4, c = (f & 15) * 4;
            KVs[r * PAD + c + 0] = vreg[i].x;
            KVs[r * PAD + c + 1] = vreg[i].y;
            KVs[r * PAD + c + 2] = vreg[i].z;
            KVs[r * PAD + c + 3] = vreg[i].w;
        }
        __syncthreads();

        // --- O += P V (64x64x64) ---
        #pragma unroll 16
        for (int n = 0; n < 64; n++) {
            float pv[4], vv[4];
            #pragma unroll
            for (int i = 0; i < 4; i++) pv[i] = Ps[(ty * 4 + i) * PAD + n];
            #pragma unroll
            for (int j = 0; j < 4; j++) vv[j] = KVs[n * PAD + tx * 4 + j];
            #pragma unroll
            for (int i = 0; i < 4; i++)
                #pragma unroll
                for (int j = 0; j < 4; j++)
                    acc[i][j] += pv[i] * vv[j];
        }
    }

    // Epilogue: normalize, write to g_attn in [B,S,D] layout.
    const int b = bh >> 4, h = bh & (H - 1);
    #pragma unroll
    for (int i = 0; i < 4; i++) {
        float inv = 1.0f / row_l[i];
        int srow = qtile * 64 + ty * 4 + i;
        #pragma unroll
        for (int j = 0; j < 4; j++) {
            g_attn[(size_t)(b * S + srow) * D + h * DK + tx * 4 + j] =
                acc[i][j] * inv;
        }
    }
}

// ---------------------------------------------------------------------------
extern "C" void kernel_launch(void* const* d_in, const int* in_sizes, int n_in,
                              void* d_out, int out_size)
{
    const float* Q  = (const float*)d_in[0];
    const float* K  = (const float*)d_in[1];
    const float* V  = (const float*)d_in[2];
    const float* Wq = (const float*)d_in[3];
    const float* Wk = (const float*)d_in[4];
    const float* Wv = (const float*)d_in[5];
    const float* Wo = (const float*)d_in[6];
    const float* bo = (const float*)d_in[7];
    float* out = (float*)d_out;

    (void)in_sizes; (void)n_in; (void)out_size;

    // Idempotent; needed because ATTN_SMEM (49920 B) exceeds the 48 KB default.
    cudaFuncSetAttribute(flash_attn_kernel,
                         cudaFuncAttributeMaxDynamicSharedMemorySize, ATTN_SMEM);

    qkv_proj_kernel<<<dim3(D / BN, M / BM, 3), 256>>>(Q, K, V, Wq, Wk, Wv);
    flash_attn_kernel<<<dim3(S / 64, B * H), 256, ATTN_SMEM>>>();
    out_proj_kernel<<<dim3(D / BN, M / BM), 256>>>(Wo, bo, out);
}

// round 3
// speedup vs baseline: 1.4166x; 1.4166x over previous
#include <cuda_runtime.h>
#include <cuda_bf16.h>
#include <cstdint>

// Problem constants
static constexpr int B  = 2;
static constexpr int S  = 2048;
static constexpr int D  = 1024;
static constexpr int H  = 16;
static constexpr int DK = 64;
static constexpr int M  = B * S;   // 4096

// ---------------------------------------------------------------------------
// Device scratch (no allocation allowed)
// ---------------------------------------------------------------------------
__device__ float g_q[(size_t)B * H * S * DK];    // [B,H,S,DK]
__device__ float g_k[(size_t)B * H * S * DK];
__device__ float g_v[(size_t)B * H * S * DK];
__device__ float g_attn[(size_t)B * S * D];      // [B,S,D]

// bf16 split operands: A slots (0..2 = Q,K,V inputs; slot 0 reused for attn out)
__device__ __nv_bfloat16 g_Ahi[3 * (size_t)M * D];
__device__ __nv_bfloat16 g_Alo[3 * (size_t)M * D];
// W transposed [N,K], slots 0..3 = Wq,Wk,Wv,Wo
__device__ __nv_bfloat16 g_Bhi[4 * (size_t)D * D];
__device__ __nv_bfloat16 g_Blo[4 * (size_t)D * D];

// ---------------------------------------------------------------------------
// PTX helpers (base-arch only: mma.sync / ldmatrix / cp.async — no tcgen05)
// ---------------------------------------------------------------------------
__device__ __forceinline__ uint32_t smem_u32(const void* p) {
    uint32_t a;
    asm("{ .reg .u64 t; cvta.to.shared.u64 t, %1; cvt.u32.u64 %0, t; }"
        : "=r"(a) : "l"(p));
    return a;
}
__device__ __forceinline__ void cp16(uint32_t saddr, const void* g) {
    asm volatile("cp.async.cg.shared.global [%0], [%1], 16;"
                 :: "r"(saddr), "l"(g) : "memory");
}
__device__ __forceinline__ void cp_commit() {
    asm volatile("cp.async.commit_group;" ::: "memory");
}
template <int N>
__device__ __forceinline__ void cp_wait() {
    asm volatile("cp.async.wait_group %0;" :: "n"(N) : "memory");
}
__device__ __forceinline__ void ldm_x4(uint32_t& r0, uint32_t& r1,
                                       uint32_t& r2, uint32_t& r3, uint32_t a) {
    asm volatile("ldmatrix.sync.aligned.m8n8.x4.shared.b16 {%0,%1,%2,%3}, [%4];"
                 : "=r"(r0), "=r"(r1), "=r"(r2), "=r"(r3) : "r"(a));
}
__device__ __forceinline__ void mma_16816(float& c0, float& c1, float& c2, float& c3,
                                          uint32_t a0, uint32_t a1, uint32_t a2,
                                          uint32_t a3, uint32_t b0, uint32_t b1) {
    asm volatile(
        "mma.sync.aligned.m16n8k16.row.col.f32.bf16.bf16.f32 "
        "{%0,%1,%2,%3}, {%4,%5,%6,%7}, {%8,%9}, {%0,%1,%2,%3};"
        : "+f"(c0), "+f"(c1), "+f"(c2), "+f"(c3)
        : "r"(a0), "r"(a1), "r"(a2), "r"(a3), "r"(b0), "r"(b1));
}

// ---------------------------------------------------------------------------
// fp32 -> bf16 hi/lo convert kernels
// ---------------------------------------------------------------------------
template <bool FROM_ATTN>
__global__ __launch_bounds__(256) void convert_a_kernel(
    const float* __restrict__ p0, const float* __restrict__ p1,
    const float* __restrict__ p2)
{
    const int z = blockIdx.z;
    const float* src = FROM_ATTN ? g_attn : (z == 0 ? p0 : z == 1 ? p1 : p2);
    const size_t base = (size_t)z * ((size_t)M * D);
    const size_t i = ((size_t)blockIdx.x * 256 + threadIdx.x) * 4;
    float4 v = *(const float4*)(src + i);

    __nv_bfloat16 hi[4], lo[4];
    float x[4] = {v.x, v.y, v.z, v.w};
    #pragma unroll
    for (int j = 0; j < 4; j++) {
        hi[j] = __float2bfloat16(x[j]);
        lo[j] = __float2bfloat16(x[j] - __bfloat162float(hi[j]));
    }
    *(uint2*)&g_Ahi[base + i] = *(uint2*)hi;
    *(uint2*)&g_Alo[base + i] = *(uint2*)lo;
}

// Transpose + split W: Wt[n][k] = W[k][n]
__global__ void convert_w_kernel(const float* __restrict__ w0,
                                 const float* __restrict__ w1,
                                 const float* __restrict__ w2,
                                 const float* __restrict__ w3)
{
    __shared__ float t[32][33];
    const int z = blockIdx.z;
    const float* W = z == 0 ? w0 : z == 1 ? w1 : z == 2 ? w2 : w3;
    const size_t base = (size_t)z * D * D;
    const int n0 = blockIdx.x * 32, k0 = blockIdx.y * 32;

    for (int i = threadIdx.y; i < 32; i += 8)
        t[i][threadIdx.x] = W[(size_t)(k0 + i) * D + n0 + threadIdx.x];
    __syncthreads();
    for (int i = threadIdx.y; i < 32; i += 8) {
        float x = t[threadIdx.x][i];            // W[k0+tx][n0+i]
        __nv_bfloat16 h = __float2bfloat16(x);
        size_t o = base + (size_t)(n0 + i) * D + k0 + threadIdx.x;
        g_Bhi[o] = h;
        g_Blo[o] = __float2bfloat16(x - __bfloat162float(h));
    }
}

// ---------------------------------------------------------------------------
// bf16 mma.sync GEMM with 3-term split. CTA 128x128, BK=32, 8 warps (64x32).
// SMEM rows have 80B stride (32 bf16 data + 16B pad) -> conflict-free ldmatrix.
// MODE 0: qkv projections (grid.z selects tensor; scatter to [B,H,S,DK])
// MODE 1: out projection (+bias, row-major out)
// ---------------------------------------------------------------------------
static constexpr int GBM = 128, GBN = 128, GBK = 32;
static constexpr int NC = D / GBK;                 // 32 chunks
static constexpr int RSTRIDE = 80;                 // bytes per smem row
static constexpr int TILE_B  = 128 * RSTRIDE;      // 10240
static constexpr int OA_HI = 0, OA_LO = TILE_B, OB_HI = 2 * TILE_B, OB_LO = 3 * TILE_B;
static constexpr int STG = 4 * TILE_B;             // 40960 per stage
static constexpr int GEMM_SMEM = 2 * STG;          // 81920

// load one 128x32 bf16 tile (global row-major, ld = D) into smem with pad
__device__ __forceinline__ void load_tile(const __nv_bfloat16* __restrict__ src,
                                          int row0, int k0, uint32_t sdst, int tid)
{
    #pragma unroll
    for (int i = 0; i < 2; i++) {
        int unit = tid + 256 * i;
        int r = unit >> 2, c = unit & 3;
        cp16(sdst + r * RSTRIDE + c * 16,
             src + (size_t)(row0 + r) * D + k0 + c * 8);
    }
}

template <int MODE>
__global__ __launch_bounds__(256, 1) void tc_gemm_kernel(
    float* __restrict__ out_param, const float* __restrict__ bias)
{
    extern __shared__ char smc[];
    const uint32_t sb = smem_u32(smc);
    const int tid = threadIdx.x;
    const int lane = tid & 31, wid = tid >> 5;
    const int z = blockIdx.z;
    const int bm = blockIdx.y * GBM;
    const int bn = blockIdx.x * GBN;

    const __nv_bfloat16* Ahi = g_Ahi + (MODE == 0 ? (size_t)z * M * D : 0);
    const __nv_bfloat16* Alo = g_Alo + (MODE == 0 ? (size_t)z * M * D : 0);
    const __nv_bfloat16* Bhi = g_Bhi + (MODE == 0 ? (size_t)z * D * D : (size_t)3 * D * D);
    const __nv_bfloat16* Blo = g_Blo + (MODE == 0 ? (size_t)z * D * D : (size_t)3 * D * D);
    float* dst = (MODE == 0) ? (z == 0 ? g_q : z == 1 ? g_k : g_v) : out_param;

    const int m_warp = (wid & 1) * 64;
    const int n_warp = (wid >> 1) * 32;

    // ldmatrix lane-dependent byte offsets
    const uint32_t a_lane = (uint32_t)((lane & 15) * RSTRIDE + ((lane >> 4) & 1) * 16);
    const uint32_t b_lane = (uint32_t)((((lane >> 4) & 1) * 8 + (lane & 7)) * RSTRIDE
                                       + ((lane >> 3) & 1) * 16);

    float acc[4][4][4];
    #pragma unroll
    for (int i = 0; i < 4; i++)
        #pragma unroll
        for (int j = 0; j < 4; j++)
            #pragma unroll
            for (int e = 0; e < 4; e++) acc[i][j][e] = 0.f;

    // prologue: chunk 0 -> stage 0
    load_tile(Ahi, bm, 0, sb + OA_HI, tid);
    load_tile(Alo, bm, 0, sb + OA_LO, tid);
    load_tile(Bhi, bn, 0, sb + OB_HI, tid);
    load_tile(Blo, bn, 0, sb + OB_LO, tid);
    cp_commit();

    for (int c = 0; c < NC; c++) {
        const int s = c & 1;
        if (c + 1 < NC) {
            const uint32_t nb = sb + (s ^ 1) * STG;
            const int k0 = (c + 1) * GBK;
            load_tile(Ahi, bm, k0, nb + OA_HI, tid);
            load_tile(Alo, bm, k0, nb + OA_LO, tid);
            load_tile(Bhi, bn, k0, nb + OB_HI, tid);
            load_tile(Blo, bn, k0, nb + OB_LO, tid);
            cp_commit();
            cp_wait<1>();
        } else {
            cp_wait<0>();
        }
        __syncthreads();

        const uint32_t stg = sb + s * STG;
        #pragma unroll
        for (int t = 0; t < 2; t++) {
            #pragma unroll
            for (int term = 0; term < 3; term++) {
                const uint32_t aoff = (term == 2) ? OA_LO : OA_HI;
                const uint32_t boff = (term == 1) ? OB_LO : OB_HI;
                uint32_t af[4][4];
                #pragma unroll
                for (int i = 0; i < 4; i++)
                    ldm_x4(af[i][0], af[i][1], af[i][2], af[i][3],
                           stg + aoff + (uint32_t)((m_warp + i * 16) * RSTRIDE + t * 32) + a_lane);
                uint32_t bf[8];
                #pragma unroll
                for (int p = 0; p < 2; p++)
                    ldm_x4(bf[p * 4 + 0], bf[p * 4 + 1], bf[p * 4 + 2], bf[p * 4 + 3],
                           stg + boff + (uint32_t)((n_warp + p * 16) * RSTRIDE + t * 32) + b_lane);
                #pragma unroll
                for (int i = 0; i < 4; i++)
                    #pragma unroll
                    for (int j = 0; j < 4; j++) {
                        const int bi = (j >> 1) * 4 + (j & 1) * 2;
                        mma_16816(acc[i][j][0], acc[i][j][1], acc[i][j][2], acc[i][j][3],
                                  af[i][0], af[i][1], af[i][2], af[i][3],
                                  bf[bi], bf[bi + 1]);
                    }
            }
        }
        __syncthreads();
    }

    // Epilogue: direct register -> global stores (float2 pairs, n even)
    const int g = lane >> 2, tq = lane & 3;
    #pragma unroll
    for (int i = 0; i < 4; i++) {
        #pragma unroll
        for (int j = 0; j < 4; j++) {
            const int n = bn + n_warp + j * 8 + tq * 2;
            #pragma unroll
            for (int half = 0; half < 2; half++) {
                const int m = bm + m_warp + i * 16 + g + half * 8;
                float2 v = make_float2(acc[i][j][half * 2], acc[i][j][half * 2 + 1]);
                if (MODE == 0) {
                    const int bb = m >> 11, ss = m & (S - 1);
                    const int h = n >> 6, d0 = n & (DK - 1);
                    *(float2*)(dst + (((size_t)(bb * H + h) * S + ss) * DK + d0)) = v;
                } else {
                    float2 bv = *(const float2*)(bias + n);
                    v.x += bv.x; v.y += bv.y;
                    *(float2*)(dst + (size_t)m * D + n) = v;
                }
            }
        }
    }
}

// ---------------------------------------------------------------------------
// Flash attention, fp32 (unchanged — known correct)
// ---------------------------------------------------------------------------
static constexpr int PAD = 65;
static constexpr int ATTN_SMEM = 3 * 64 * PAD * (int)sizeof(float);  // 49920 B

__global__ __launch_bounds__(256) void flash_attn_kernel()
{
    extern __shared__ float smf[];
    float* Qs  = smf;
    float* KVs = smf + 64 * PAD;
    float* Ps  = smf + 2 * 64 * PAD;

    const int tid = threadIdx.x;
    const int ty = tid >> 4, tx = tid & 15;
    const int qtile = (int)gridDim.x - 1 - (int)blockIdx.x;
    const int bh = blockIdx.y;

    const float* qp = g_q + (size_t)bh * S * DK + (size_t)qtile * 64 * DK;
    const float* kp = g_k + (size_t)bh * S * DK;
    const float* vp = g_v + (size_t)bh * S * DK;

    #pragma unroll
    for (int i = 0; i < 4; i++) {
        int f = tid + 256 * i;
        int r = f >> 4, c = (f & 15) * 4;
        float4 v4 = *(const float4*)(qp + r * DK + c);
        Qs[r * PAD + c + 0] = v4.x;
        Qs[r * PAD + c + 1] = v4.y;
        Qs[r * PAD + c + 2] = v4.z;
        Qs[r * PAD + c + 3] = v4.w;
    }

    float row_m[4], row_l[4], acc[4][4];
    #pragma unroll
    for (int i = 0; i < 4; i++) {
        row_m[i] = -1e30f;
        row_l[i] = 0.f;
        #pragma unroll
        for (int j = 0; j < 4; j++) acc[i][j] = 0.f;
    }
    __syncthreads();

    for (int nt = 0; nt <= qtile; nt++) {
        const float* kt = kp + (size_t)nt * 64 * DK;
        float4 kreg[4];
        #pragma unroll
        for (int i = 0; i < 4; i++) {
            int f = tid + 256 * i;
            kreg[i] = *(const float4*)(kt + (f >> 4) * DK + (f & 15) * 4);
        }
        __syncthreads();
        #pragma unroll
        for (int i = 0; i < 4; i++) {
            int f = tid + 256 * i;
            int r = f >> 4, c = (f & 15) * 4;
            KVs[r * PAD + c + 0] = kreg[i].x;
            KVs[r * PAD + c + 1] = kreg[i].y;
            KVs[r * PAD + c + 2] = kreg[i].z;
            KVs[r * PAD + c + 3] = kreg[i].w;
        }
        __syncthreads();

        float sv[4][4];
        #pragma unroll
        for (int i = 0; i < 4; i++)
            #pragma unroll
            for (int j = 0; j < 4; j++) sv[i][j] = 0.f;

        #pragma unroll 16
        for (int d = 0; d < DK; d++) {
            float qv[4], kv[4];
            #pragma unroll
            for (int i = 0; i < 4; i++) qv[i] = Qs[(ty * 4 + i) * PAD + d];
            #pragma unroll
            for (int j = 0; j < 4; j++) kv[j] = KVs[(tx * 4 + j) * PAD + d];
            #pragma unroll
            for (int i = 0; i < 4; i++)
                #pragma unroll
                for (int j = 0; j < 4; j++)
                    sv[i][j] += qv[i] * kv[j];
        }

        const bool diag = (nt == qtile);
        #pragma unroll
        for (int i = 0; i < 4; i++)
            #pragma unroll
            for (int j = 0; j < 4; j++) {
                float x = sv[i][j] * 0.125f;
                if (diag && (tx * 4 + j) > (ty * 4 + i)) x = -1e30f;
                sv[i][j] = x;
            }

        #pragma unroll
        for (int i = 0; i < 4; i++) {
            float mx = fmaxf(fmaxf(sv[i][0], sv[i][1]), fmaxf(sv[i][2], sv[i][3]));
            #pragma unroll
            for (int off = 8; off >= 1; off >>= 1)
                mx = fmaxf(mx, __shfl_xor_sync(0xffffffffu, mx, off, 16));
            float m_new = fmaxf(row_m[i], mx);
            float sc = __expf(row_m[i] - m_new);
            float sum = 0.f;
            #pragma unroll
            for (int j = 0; j < 4; j++) {
                float p = __expf(sv[i][j] - m_new);
                Ps[(ty * 4 + i) * PAD + tx * 4 + j] = p;
                sum += p;
            }
            #pragma unroll
            for (int off = 8; off >= 1; off >>= 1)
                sum += __shfl_xor_sync(0xffffffffu, sum, off, 16);
            row_l[i] = row_l[i] * sc + sum;
            row_m[i] = m_new;
            #pragma unroll
            for (int j = 0; j < 4; j++) acc[i][j] *= sc;
        }

        const float* vt = vp + (size_t)nt * 64 * DK;
        float4 vreg[4];
        #pragma unroll
        for (int i = 0; i < 4; i++) {
            int f = tid + 256 * i;
            vreg[i] = *(const float4*)(vt + (f >> 4) * DK + (f & 15) * 4);
        }
        __syncthreads();
        #pragma unroll
        for (int i = 0; i < 4; i++) {
            int f = tid + 256 * i;
            int r = f >> 4, c = (f & 15) * 4;
            KVs[r * PAD + c + 0] = vreg[i].x;
            KVs[r * PAD + c + 1] = vreg[i].y;
            KVs[r * PAD + c + 2] = vreg[i].z;
            KVs[r * PAD + c + 3] = vreg[i].w;
        }
        __syncthreads();

        #pragma unroll 16
        for (int n = 0; n < 64; n++) {
            float pv[4], vv[4];
            #pragma unroll
            for (int i = 0; i < 4; i++) pv[i] = Ps[(ty * 4 + i) * PAD + n];
            #pragma unroll
            for (int j = 0; j < 4; j++) vv[j] = KVs[n * PAD + tx * 4 + j];
            #pragma unroll
            for (int i = 0; i < 4; i++)
                #pragma unroll
                for (int j = 0; j < 4; j++)
                    acc[i][j] += pv[i] * vv[j];
        }
    }

    const int b = bh >> 4, h = bh & (H - 1);
    #pragma unroll
    for (int i = 0; i < 4; i++) {
        float inv = 1.0f / row_l[i];
        int srow = qtile * 64 + ty * 4 + i;
        #pragma unroll
        for (int j = 0; j < 4; j++) {
            g_attn[(size_t)(b * S + srow) * D + h * DK + tx * 4 + j] =
                acc[i][j] * inv;
        }
    }
}

// ---------------------------------------------------------------------------
extern "C" void kernel_launch(void* const* d_in, const int* in_sizes, int n_in,
                              void* d_out, int out_size)
{
    const float* Q  = (const float*)d_in[0];
    const float* K  = (const float*)d_in[1];
    const float* V  = (const float*)d_in[2];
    const float* Wq = (const float*)d_in[3];
    const float* Wk = (const float*)d_in[4];
    const float* Wv = (const float*)d_in[5];
    const float* Wo = (const float*)d_in[6];
    const float* bo = (const float*)d_in[7];
    float* out = (float*)d_out;

    (void)in_sizes; (void)n_in; (void)out_size;

    cudaFuncSetAttribute(tc_gemm_kernel<0>,
                         cudaFuncAttributeMaxDynamicSharedMemorySize, GEMM_SMEM);
    cudaFuncSetAttribute(tc_gemm_kernel<1>,
                         cudaFuncAttributeMaxDynamicSharedMemorySize, GEMM_SMEM);
    cudaFuncSetAttribute(flash_attn_kernel,
                         cudaFuncAttributeMaxDynamicSharedMemorySize, ATTN_SMEM);

    // fp32 -> bf16 hi/lo conversions
    convert_a_kernel<false><<<dim3(M * D / (256 * 4), 1, 3), 256>>>(Q, K, V);
    convert_w_kernel<<<dim3(D / 32, D / 32, 4), dim3(32, 8)>>>(Wq, Wk, Wv, Wo);

    // Q/K/V projections on tensor cores (HMMA via mma.sync)
    tc_gemm_kernel<0><<<dim3(D / GBN, M / GBM, 3), 256, GEMM_SMEM>>>(nullptr, nullptr);

    // Attention (fp32 SIMT)
    flash_attn_kernel<<<dim3(S / 64, B * H), 256, ATTN_SMEM>>>();

    // Convert attention output, then output projection (+bias)
    convert_a_kernel<true><<<dim3(M * D / (256 * 4), 1, 1), 256>>>(nullptr, nullptr, nullptr);
    tc_gemm_kernel<1><<<dim3(D / GBN, M / GBM, 1), 256, GEMM_SMEM>>>(out, bo);
}

// round 4
// speedup vs baseline: 2.4168x; 1.7060x over previous
#include <cuda_runtime.h>
#include <cuda_bf16.h>
#include <cstdint>

// Problem constants
static constexpr int B  = 2;
static constexpr int S  = 2048;
static constexpr int D  = 1024;
static constexpr int H  = 16;
static constexpr int DK = 64;
static constexpr int M  = B * S;   // 4096

// ---------------------------------------------------------------------------
// Device scratch (no allocation allowed)
// ---------------------------------------------------------------------------
__device__ float g_attn[(size_t)B * S * D];      // [B,S,D] attention output fp32

// q/k/v in bf16 hi/lo split, [B,H,S,DK]
__device__ __nv_bfloat16 g_qhi[(size_t)B * H * S * DK];
__device__ __nv_bfloat16 g_qlo[(size_t)B * H * S * DK];
__device__ __nv_bfloat16 g_khi[(size_t)B * H * S * DK];
__device__ __nv_bfloat16 g_klo[(size_t)B * H * S * DK];
__device__ __nv_bfloat16 g_vhi[(size_t)B * H * S * DK];
__device__ __nv_bfloat16 g_vlo[(size_t)B * H * S * DK];

// bf16 split GEMM A operands: slots 0..2 = Q,K,V inputs; slot 0 reused for attn out
__device__ __nv_bfloat16 g_Ahi[3 * (size_t)M * D];
__device__ __nv_bfloat16 g_Alo[3 * (size_t)M * D];
// W transposed [N,K], slots 0..3 = Wq,Wk,Wv,Wo
__device__ __nv_bfloat16 g_Bhi[4 * (size_t)D * D];
__device__ __nv_bfloat16 g_Blo[4 * (size_t)D * D];

// ---------------------------------------------------------------------------
// PTX helpers (base-arch only: mma.sync / ldmatrix / cp.async)
// ---------------------------------------------------------------------------
__device__ __forceinline__ uint32_t smem_u32(const void* p) {
    uint32_t a;
    asm("{ .reg .u64 t; cvta.to.shared.u64 t, %1; cvt.u32.u64 %0, t; }"
        : "=r"(a) : "l"(p));
    return a;
}
__device__ __forceinline__ void cp16(uint32_t saddr, const void* g) {
    asm volatile("cp.async.cg.shared.global [%0], [%1], 16;"
                 :: "r"(saddr), "l"(g) : "memory");
}
__device__ __forceinline__ void cp_commit() {
    asm volatile("cp.async.commit_group;" ::: "memory");
}
template <int N>
__device__ __forceinline__ void cp_wait() {
    asm volatile("cp.async.wait_group %0;" :: "n"(N) : "memory");
}
__device__ __forceinline__ void ldm_x4(uint32_t& r0, uint32_t& r1,
                                       uint32_t& r2, uint32_t& r3, uint32_t a) {
    asm volatile("ldmatrix.sync.aligned.m8n8.x4.shared.b16 {%0,%1,%2,%3}, [%4];"
                 : "=r"(r0), "=r"(r1), "=r"(r2), "=r"(r3) : "r"(a));
}
__device__ __forceinline__ void ldm_x4_t(uint32_t& r0, uint32_t& r1,
                                         uint32_t& r2, uint32_t& r3, uint32_t a) {
    asm volatile("ldmatrix.sync.aligned.m8n8.x4.trans.shared.b16 {%0,%1,%2,%3}, [%4];"
                 : "=r"(r0), "=r"(r1), "=r"(r2), "=r"(r3) : "r"(a));
}
__device__ __forceinline__ void mma_16816(float& c0, float& c1, float& c2, float& c3,
                                          uint32_t a0, uint32_t a1, uint32_t a2,
                                          uint32_t a3, uint32_t b0, uint32_t b1) {
    asm volatile(
        "mma.sync.aligned.m16n8k16.row.col.f32.bf16.bf16.f32 "
        "{%0,%1,%2,%3}, {%4,%5,%6,%7}, {%8,%9}, {%0,%1,%2,%3};"
        : "+f"(c0), "+f"(c1), "+f"(c2), "+f"(c3)
        : "r"(a0), "r"(a1), "r"(a2), "r"(a3), "r"(b0), "r"(b1));
}

// ---------------------------------------------------------------------------
// fp32 -> bf16 hi/lo convert kernels
// ---------------------------------------------------------------------------
template <bool FROM_ATTN>
__global__ __launch_bounds__(256) void convert_a_kernel(
    const float* __restrict__ p0, const float* __restrict__ p1,
    const float* __restrict__ p2)
{
    const int z = blockIdx.z;
    const float* src = FROM_ATTN ? g_attn : (z == 0 ? p0 : z == 1 ? p1 : p2);
    const size_t base = (size_t)z * ((size_t)M * D);
    const size_t i = ((size_t)blockIdx.x * 256 + threadIdx.x) * 4;
    float4 v = *(const float4*)(src + i);

    __nv_bfloat16 hi[4], lo[4];
    float x[4] = {v.x, v.y, v.z, v.w};
    #pragma unroll
    for (int j = 0; j < 4; j++) {
        hi[j] = __float2bfloat16(x[j]);
        lo[j] = __float2bfloat16(x[j] - __bfloat162float(hi[j]));
    }
    *(uint2*)&g_Ahi[base + i] = *(uint2*)hi;
    *(uint2*)&g_Alo[base + i] = *(uint2*)lo;
}

// Transpose + split W: Wt[n][k] = W[k][n]
__global__ void convert_w_kernel(const float* __restrict__ w0,
                                 const float* __restrict__ w1,
                                 const float* __restrict__ w2,
                                 const float* __restrict__ w3)
{
    __shared__ float t[32][33];
    const int z = blockIdx.z;
    const float* W = z == 0 ? w0 : z == 1 ? w1 : z == 2 ? w2 : w3;
    const size_t base = (size_t)z * D * D;
    const int n0 = blockIdx.x * 32, k0 = blockIdx.y * 32;

    for (int i = threadIdx.y; i < 32; i += 8)
        t[i][threadIdx.x] = W[(size_t)(k0 + i) * D + n0 + threadIdx.x];
    __syncthreads();
    for (int i = threadIdx.y; i < 32; i += 8) {
        float x = t[threadIdx.x][i];
        __nv_bfloat16 h = __float2bfloat16(x);
        size_t o = base + (size_t)(n0 + i) * D + k0 + threadIdx.x;
        g_Bhi[o] = h;
        g_Blo[o] = __float2bfloat16(x - __bfloat162float(h));
    }
}

// ---------------------------------------------------------------------------
// bf16 mma.sync GEMM with 3-term split. CTA 128x128, BK=32, 8 warps (64x32).
// MODE 0: qkv projections -> write bf16 hi/lo split directly to [B,H,S,DK]
// MODE 1: out projection (+bias, row-major fp32 out)
// ---------------------------------------------------------------------------
static constexpr int GBM = 128, GBN = 128, GBK = 32;
static constexpr int NC = D / GBK;                 // 32 chunks
static constexpr int RSTRIDE = 80;                 // bytes per smem row
static constexpr int TILE_B  = 128 * RSTRIDE;      // 10240
static constexpr int OA_HI = 0, OA_LO = TILE_B, OB_HI = 2 * TILE_B, OB_LO = 3 * TILE_B;
static constexpr int STG = 4 * TILE_B;             // 40960 per stage
static constexpr int GEMM_SMEM = 2 * STG;          // 81920

__device__ __forceinline__ void load_tile(const __nv_bfloat16* __restrict__ src,
                                          int row0, int k0, uint32_t sdst, int tid)
{
    #pragma unroll
    for (int i = 0; i < 2; i++) {
        int unit = tid + 256 * i;
        int r = unit >> 2, c = unit & 3;
        cp16(sdst + r * RSTRIDE + c * 16,
             src + (size_t)(row0 + r) * D + k0 + c * 8);
    }
}

template <int MODE>
__global__ __launch_bounds__(256, 1) void tc_gemm_kernel(
    float* __restrict__ out_param, const float* __restrict__ bias)
{
    extern __shared__ char smc[];
    const uint32_t sb = smem_u32(smc);
    const int tid = threadIdx.x;
    const int lane = tid & 31, wid = tid >> 5;
    const int z = blockIdx.z;
    const int bm = blockIdx.y * GBM;
    const int bn = blockIdx.x * GBN;

    const __nv_bfloat16* Ahi = g_Ahi + (MODE == 0 ? (size_t)z * M * D : 0);
    const __nv_bfloat16* Alo = g_Alo + (MODE == 0 ? (size_t)z * M * D : 0);
    const __nv_bfloat16* Bhi = g_Bhi + (MODE == 0 ? (size_t)z * D * D : (size_t)3 * D * D);
    const __nv_bfloat16* Blo = g_Blo + (MODE == 0 ? (size_t)z * D * D : (size_t)3 * D * D);

    const int m_warp = (wid & 1) * 64;
    const int n_warp = (wid >> 1) * 32;

    const uint32_t a_lane = (uint32_t)((lane & 15) * RSTRIDE + ((lane >> 4) & 1) * 16);
    const uint32_t b_lane = (uint32_t)((((lane >> 4) & 1) * 8 + (lane & 7)) * RSTRIDE
                                       + ((lane >> 3) & 1) * 16);

    float acc[4][4][4];
    #pragma unroll
    for (int i = 0; i < 4; i++)
        #pragma unroll
        for (int j = 0; j < 4; j++)
            #pragma unroll
            for (int e = 0; e < 4; e++) acc[i][j][e] = 0.f;

    load_tile(Ahi, bm, 0, sb + OA_HI, tid);
    load_tile(Alo, bm, 0, sb + OA_LO, tid);
    load_tile(Bhi, bn, 0, sb + OB_HI, tid);
    load_tile(Blo, bn, 0, sb + OB_LO, tid);
    cp_commit();

    for (int c = 0; c < NC; c++) {
        const int s = c & 1;
        if (c + 1 < NC) {
            const uint32_t nb = sb + (s ^ 1) * STG;
            const int k0 = (c + 1) * GBK;
            load_tile(Ahi, bm, k0, nb + OA_HI, tid);
            load_tile(Alo, bm, k0, nb + OA_LO, tid);
            load_tile(Bhi, bn, k0, nb + OB_HI, tid);
            load_tile(Blo, bn, k0, nb + OB_LO, tid);
            cp_commit();
            cp_wait<1>();
        } else {
            cp_wait<0>();
        }
        __syncthreads();

        const uint32_t stg = sb + s * STG;
        #pragma unroll
        for (int t = 0; t < 2; t++) {
            #pragma unroll
            for (int term = 0; term < 3; term++) {
                const uint32_t aoff = (term == 2) ? OA_LO : OA_HI;
                const uint32_t boff = (term == 1) ? OB_LO : OB_HI;
                uint32_t af[4][4];
                #pragma unroll
                for (int i = 0; i < 4; i++)
                    ldm_x4(af[i][0], af[i][1], af[i][2], af[i][3],
                           stg + aoff + (uint32_t)((m_warp + i * 16) * RSTRIDE + t * 32) + a_lane);
                uint32_t bf[8];
                #pragma unroll
                for (int p = 0; p < 2; p++)
                    ldm_x4(bf[p * 4 + 0], bf[p * 4 + 1], bf[p * 4 + 2], bf[p * 4 + 3],
                           stg + boff + (uint32_t)((n_warp + p * 16) * RSTRIDE + t * 32) + b_lane);
                #pragma unroll
                for (int i = 0; i < 4; i++)
                    #pragma unroll
                    for (int j = 0; j < 4; j++) {
                        const int bi = (j >> 1) * 4 + (j & 1) * 2;
                        mma_16816(acc[i][j][0], acc[i][j][1], acc[i][j][2], acc[i][j][3],
                                  af[i][0], af[i][1], af[i][2], af[i][3],
                                  bf[bi], bf[bi + 1]);
                    }
            }
        }
        __syncthreads();
    }

    // Epilogue
    const int g = lane >> 2, tq = lane & 3;
    #pragma unroll
    for (int i = 0; i < 4; i++) {
        #pragma unroll
        for (int j = 0; j < 4; j++) {
            const int n = bn + n_warp + j * 8 + tq * 2;
            #pragma unroll
            for (int half = 0; half < 2; half++) {
                const int m = bm + m_warp + i * 16 + g + half * 8;
                float2 v = make_float2(acc[i][j][half * 2], acc[i][j][half * 2 + 1]);
                if (MODE == 0) {
                    __nv_bfloat16* dhi = z == 0 ? g_qhi : z == 1 ? g_khi : g_vhi;
                    __nv_bfloat16* dlo = z == 0 ? g_qlo : z == 1 ? g_klo : g_vlo;
                    const int bb = m >> 11, ss = m & (S - 1);
                    const int h = n >> 6, d0 = n & (DK - 1);
                    const size_t idx = ((size_t)(bb * H + h) * S + ss) * DK + d0;
                    __nv_bfloat162 hv = __float22bfloat162_rn(v);
                    float2 hf = __bfloat1622float2(hv);
                    __nv_bfloat162 lv = __float22bfloat162_rn(
                        make_float2(v.x - hf.x, v.y - hf.y));
                    *(__nv_bfloat162*)(dhi + idx) = hv;
                    *(__nv_bfloat162*)(dlo + idx) = lv;
                } else {
                    float2 bv = *(const float2*)(bias + n);
                    v.x += bv.x; v.y += bv.y;
                    *(float2*)(out_param + (size_t)m * D + n) = v;
                }
            }
        }
    }
}

// ---------------------------------------------------------------------------
// Tensor-core flash attention (FA2-style, bf16 mma.sync, 3-term split).
// CTA: 256 threads = 8 warps, 128 Q rows (m16 per warp), 64-key tiles.
// ---------------------------------------------------------------------------
static constexpr int RST = 144;                 // smem row stride (bytes)
static constexpr int KV_TERM = 64 * RST;        // 9216 per tile-term
static constexpr int KV_STG  = 4 * KV_TERM;     // khi,klo,vhi,vlo = 36864
static constexpr int ATTN_SMEM = 2 * KV_STG;    // 73728

__global__ __launch_bounds__(256, 1) void flash_attn_tc()
{
    extern __shared__ char smc[];
    const uint32_t sb = smem_u32(smc);
    const int tid = threadIdx.x, lane = tid & 31, wid = tid >> 5;
    const int qb = (int)gridDim.x - 1 - (int)blockIdx.x;   // reversed: heavy first
    const int bh = blockIdx.y;
    const int ntiles = 2 * qb + 2;
    const size_t bho = (size_t)bh * S * DK;

    const __nv_bfloat16* qh_g = g_qhi + bho + (size_t)qb * 128 * DK;
    const __nv_bfloat16* ql_g = g_qlo + bho + (size_t)qb * 128 * DK;
    const __nv_bfloat16* kh_g = g_khi + bho;
    const __nv_bfloat16* kl_g = g_klo + bho;
    const __nv_bfloat16* vh_g = g_vhi + bho;
    const __nv_bfloat16* vl_g = g_vlo + bho;

    // ---- stage Q tile (128x64 hi/lo) through smem, distribute to registers ----
    #pragma unroll
    for (int i = 0; i < 4; i++) {
        int u = tid + 256 * i, r = u >> 3, c = u & 7;
        cp16(sb + r * RST + c * 16, qh_g + r * DK + c * 8);
        cp16(sb + 2 * KV_TERM + r * RST + c * 16, ql_g + r * DK + c * 8);
    }
    cp_commit(); cp_wait<0>(); __syncthreads();

    const uint32_t a_lane = (uint32_t)((lane & 15) * RST + (lane >> 4) * 16);
    uint32_t qh[4][4], ql[4][4];
    #pragma unroll
    for (int kt = 0; kt < 4; kt++) {
        ldm_x4(qh[kt][0], qh[kt][1], qh[kt][2], qh[kt][3],
               sb + (uint32_t)(wid * 16) * RST + kt * 32 + a_lane);
        ldm_x4(ql[kt][0], ql[kt][1], ql[kt][2], ql[kt][3],
               sb + 2 * KV_TERM + (uint32_t)(wid * 16) * RST + kt * 32 + a_lane);
    }
    __syncthreads();

    const uint32_t b_lane = (uint32_t)(((((lane >> 4) & 1) * 8) + (lane & 7)) * RST
                                       + ((lane >> 3) & 1) * 16);
    const uint32_t v_lane = (uint32_t)(((((lane >> 3) & 1) * 8) + (lane & 7)) * RST
                                       + (lane >> 4) * 16);

    auto load_kv = [&](int nt, uint32_t dstb) {
        const int kb0 = nt * 64;
        #pragma unroll
        for (int i = 0; i < 2; i++) {
            int u = tid + 256 * i, r = u >> 3, c = u & 7;
            size_t g = (size_t)(kb0 + r) * DK + c * 8;
            uint32_t so = dstb + (uint32_t)(r * RST + c * 16);
            cp16(so + 0 * KV_TERM, kh_g + g);
            cp16(so + 1 * KV_TERM, kl_g + g);
            cp16(so + 2 * KV_TERM, vh_g + g);
            cp16(so + 3 * KV_TERM, vl_g + g);
        }
    };

    float o[8][4];
    #pragma unroll
    for (int j = 0; j < 8; j++)
        #pragma unroll
        for (int e = 0; e < 4; e++) o[j][e] = 0.f;
    float row_m[2] = {-1e30f, -1e30f}, row_l[2] = {0.f, 0.f};
    const int m0w = qb * 128 + wid * 16;

    load_kv(0, sb);
    cp_commit();

    for (int nt = 0; nt < ntiles; nt++) {
        if (nt + 1 < ntiles) {
            load_kv(nt + 1, sb + (uint32_t)((nt + 1) & 1) * KV_STG);
            cp_commit();
            cp_wait<1>();
        } else {
            cp_wait<0>();
        }
        __syncthreads();

        const int kbase = nt * 64;
        if (kbase <= m0w + 15) {                  // warp has unmasked work
            const uint32_t stg = sb + (uint32_t)(nt & 1) * KV_STG;

            // ---- S = Q K^T, 3 terms ----
            float sc[8][4];
            #pragma unroll
            for (int j = 0; j < 8; j++)
                #pragma unroll
                for (int e = 0; e < 4; e++) sc[j][e] = 0.f;

            #pragma unroll
            for (int kt = 0; kt < 4; kt++) {
                #pragma unroll
                for (int nb = 0; nb < 4; nb++) {
                    uint32_t bk[4];
                    const uint32_t tb = (uint32_t)(nb * 16) * RST + kt * 32;
                    ldm_x4(bk[0], bk[1], bk[2], bk[3], stg + tb + b_lane);  // khi
                    #pragma unroll
                    for (int j2 = 0; j2 < 2; j2++) {
                        const int j = nb * 2 + j2;
                        mma_16816(sc[j][0], sc[j][1], sc[j][2], sc[j][3],
                                  qh[kt][0], qh[kt][1], qh[kt][2], qh[kt][3],
                                  bk[j2 * 2], bk[j2 * 2 + 1]);
                        mma_16816(sc[j][0], sc[j][1], sc[j][2], sc[j][3],
                                  ql[kt][0], ql[kt][1], ql[kt][2], ql[kt][3],
                                  bk[j2 * 2], bk[j2 * 2 + 1]);
                    }
                    ldm_x4(bk[0], bk[1], bk[2], bk[3],
                           stg + KV_TERM + tb + b_lane);                    // klo
                    #pragma unroll
                    for (int j2 = 0; j2 < 2; j2++) {
                        const int j = nb * 2 + j2;
                        mma_16816(sc[j][0], sc[j][1], sc[j][2], sc[j][3],
                                  qh[kt][0], qh[kt][1], qh[kt][2], qh[kt][3],
                                  bk[j2 * 2], bk[j2 * 2 + 1]);
                    }
                }
            }

            // scale + causal mask
            const bool needm = (kbase + 63) > m0w;
            #pragma unroll
            for (int j = 0; j < 8; j++)
                #pragma unroll
                for (int e = 0; e < 4; e++) {
                    float x = sc[j][e] * 0.125f;
                    if (needm) {
                        const int key = kbase + j * 8 + (lane & 3) * 2 + (e & 1);
                        const int row = m0w + (lane >> 2) + (e >> 1) * 8;
                        if (key > row) x = -1e30f;
                    }
                    sc[j][e] = x;
                }

            // ---- online softmax (per row-half) ----
            #pragma unroll
            for (int h2 = 0; h2 < 2; h2++) {
                float mx = -1e30f;
                #pragma unroll
                for (int j = 0; j < 8; j++)
                    mx = fmaxf(mx, fmaxf(sc[j][h2 * 2], sc[j][h2 * 2 + 1]));
                mx = fmaxf(mx, __shfl_xor_sync(0xffffffffu, mx, 1));
                mx = fmaxf(mx, __shfl_xor_sync(0xffffffffu, mx, 2));
                const float mn = fmaxf(row_m[h2], mx);
                const float corr = __expf(row_m[h2] - mn);
                float sum = 0.f;
                #pragma unroll
                for (int j = 0; j < 8; j++) {
                    float p0 = __expf(sc[j][h2 * 2] - mn);
                    float p1 = __expf(sc[j][h2 * 2 + 1] - mn);
                    sc[j][h2 * 2] = p0; sc[j][h2 * 2 + 1] = p1;
                    sum += p0 + p1;
                }
                sum += __shfl_xor_sync(0xffffffffu, sum, 1);
                sum += __shfl_xor_sync(0xffffffffu, sum, 2);
                row_l[h2] = row_l[h2] * corr + sum;
                row_m[h2] = mn;
                #pragma unroll
                for (int j = 0; j < 8; j++) {
                    o[j][h2 * 2] *= corr;
                    o[j][h2 * 2 + 1] *= corr;
                }
            }

            // ---- pack P into bf16 hi/lo A-fragments (register-only) ----
            uint32_t pHi[8][2], pLo[8][2];
            #pragma unroll
            for (int j = 0; j < 8; j++)
                #pragma unroll
                for (int pr = 0; pr < 2; pr++) {
                    float p0 = sc[j][pr * 2], p1 = sc[j][pr * 2 + 1];
                    __nv_bfloat162 hv = __float22bfloat162_rn(make_float2(p0, p1));
                    float2 hf = __bfloat1622float2(hv);
                    __nv_bfloat162 lv = __float22bfloat162_rn(
                        make_float2(p0 - hf.x, p1 - hf.y));
                    pHi[j][pr] = *(uint32_t*)&hv;
                    pLo[j][pr] = *(uint32_t*)&lv;
                }

            // ---- O += P V, 3 terms (V^T fragments via ldmatrix.trans) ----
            #pragma unroll
            for (int kt = 0; kt < 4; kt++) {
                const uint32_t ah0 = pHi[2 * kt][0], ah1 = pHi[2 * kt][1];
                const uint32_t ah2 = pHi[2 * kt + 1][0], ah3 = pHi[2 * kt + 1][1];
                const uint32_t al0 = pLo[2 * kt][0], al1 = pLo[2 * kt][1];
                const uint32_t al2 = pLo[2 * kt + 1][0], al3 = pLo[2 * kt + 1][1];
                #pragma unroll
                for (int nb = 0; nb < 4; nb++) {
                    uint32_t bv[4];
                    const uint32_t tb = (uint32_t)(kt * 16) * RST + nb * 32;
                    ldm_x4_t(bv[0], bv[1], bv[2], bv[3],
                             stg + 2 * KV_TERM + tb + v_lane);               // vhi
                    #pragma unroll
                    for (int j2 = 0; j2 < 2; j2++) {
                        const int j = nb * 2 + j2;
                        mma_16816(o[j][0], o[j][1], o[j][2], o[j][3],
                                  ah0, ah1, ah2, ah3, bv[j2 * 2], bv[j2 * 2 + 1]);
                        mma_16816(o[j][0], o[j][1], o[j][2], o[j][3],
                                  al0, al1, al2, al3, bv[j2 * 2], bv[j2 * 2 + 1]);
                    }
                    ldm_x4_t(bv[0], bv[1], bv[2], bv[3],
                             stg + 3 * KV_TERM + tb + v_lane);               // vlo
                    #pragma unroll
                    for (int j2 = 0; j2 < 2; j2++) {
                        const int j = nb * 2 + j2;
                        mma_16816(o[j][0], o[j][1], o[j][2], o[j][3],
                                  ah0, ah1, ah2, ah3, bv[j2 * 2], bv[j2 * 2 + 1]);
                    }
                }
            }
        }
        __syncthreads();
    }

    // ---- epilogue: normalize, write [B,S,D] fp32 ----
    const int b = bh >> 4, head = bh & (H - 1);
    #pragma unroll
    for (int h2 = 0; h2 < 2; h2++) {
        const float inv = 1.0f / row_l[h2];
        const int row = m0w + (lane >> 2) + h2 * 8;
        #pragma unroll
        for (int j = 0; j < 8; j++) {
            const int col = head * DK + j * 8 + (lane & 3) * 2;
            float2 v = make_float2(o[j][h2 * 2] * inv, o[j][h2 * 2 + 1] * inv);
            *(float2*)(g_attn + (size_t)(b * S + row) * D + col) = v;
        }
    }
}

// ---------------------------------------------------------------------------
extern "C" void kernel_launch(void* const* d_in, const int* in_sizes, int n_in,
                              void* d_out, int out_size)
{
    const float* Q  = (const float*)d_in[0];
    const float* K  = (const float*)d_in[1];
    const float* V  = (const float*)d_in[2];
    const float* Wq = (const float*)d_in[3];
    const float* Wk = (const float*)d_in[4];
    const float* Wv = (const float*)d_in[5];
    const float* Wo = (const float*)d_in[6];
    const float* bo = (const float*)d_in[7];
    float* out = (float*)d_out;

    (void)in_sizes; (void)n_in; (void)out_size;

    cudaFuncSetAttribute(tc_gemm_kernel<0>,
                         cudaFuncAttributeMaxDynamicSharedMemorySize, GEMM_SMEM);
    cudaFuncSetAttribute(tc_gemm_kernel<1>,
                         cudaFuncAttributeMaxDynamicSharedMemorySize, GEMM_SMEM);
    cudaFuncSetAttribute(flash_attn_tc,
                         cudaFuncAttributeMaxDynamicSharedMemorySize, ATTN_SMEM);

    // fp32 -> bf16 hi/lo conversions of inputs + weights
    convert_a_kernel<false><<<dim3(M * D / (256 * 4), 1, 3), 256>>>(Q, K, V);
    convert_w_kernel<<<dim3(D / 32, D / 32, 4), dim3(32, 8)>>>(Wq, Wk, Wv, Wo);

    // Q/K/V projections (HMMA) -> bf16 hi/lo split q,k,v
    tc_gemm_kernel<0><<<dim3(D / GBN, M / GBM, 3), 256, GEMM_SMEM>>>(nullptr, nullptr);

    // Tensor-core flash attention
    flash_attn_tc<<<dim3(S / 128, B * H), 256, ATTN_SMEM>>>();

    // Convert attention output, then output projection (+bias)
    convert_a_kernel<true><<<dim3(M * D / (256 * 4), 1, 1), 256>>>(nullptr, nullptr, nullptr);
    tc_gemm_kernel<1><<<dim3(D / GBN, M / GBM, 1), 256, GEMM_SMEM>>>(out, bo);
}

// round 6
// speedup vs baseline: 2.6260x; 1.0866x over previous
#include <cuda_runtime.h>
#include <cuda_bf16.h>
#include <cstdint>

// Problem constants
static constexpr int B  = 2;
static constexpr int S  = 2048;
static constexpr int D  = 1024;
static constexpr int H  = 16;
static constexpr int DK = 64;
static constexpr int M  = B * S;   // 4096

// ---------------------------------------------------------------------------
// Device scratch (no allocation allowed)
// ---------------------------------------------------------------------------
// q/k/v in bf16 hi/lo split, [B,H,S,DK]
__device__ __nv_bfloat16 g_qhi[(size_t)B * H * S * DK];
__device__ __nv_bfloat16 g_qlo[(size_t)B * H * S * DK];
__device__ __nv_bfloat16 g_khi[(size_t)B * H * S * DK];
__device__ __nv_bfloat16 g_klo[(size_t)B * H * S * DK];
__device__ __nv_bfloat16 g_vhi[(size_t)B * H * S * DK];
__device__ __nv_bfloat16 g_vlo[(size_t)B * H * S * DK];

// bf16 split GEMM A operands: slots 0..2 = Q,K,V inputs; slot 0 reused by
// the attention epilogue as the out-projection input.
__device__ __nv_bfloat16 g_Ahi[3 * (size_t)M * D];
__device__ __nv_bfloat16 g_Alo[3 * (size_t)M * D];
// W transposed [N,K], slots 0..3 = Wq,Wk,Wv,Wo
__device__ __nv_bfloat16 g_Bhi[4 * (size_t)D * D];
__device__ __nv_bfloat16 g_Blo[4 * (size_t)D * D];

// ---------------------------------------------------------------------------
// PTX helpers (base-arch only: mma.sync / ldmatrix / cp.async)
// ---------------------------------------------------------------------------
__device__ __forceinline__ uint32_t smem_u32(const void* p) {
    uint32_t a;
    asm("{ .reg .u64 t; cvta.to.shared.u64 t, %1; cvt.u32.u64 %0, t; }"
        : "=r"(a) : "l"(p));
    return a;
}
__device__ __forceinline__ void cp16(uint32_t saddr, const void* g) {
    asm volatile("cp.async.cg.shared.global [%0], [%1], 16;"
                 :: "r"(saddr), "l"(g) : "memory");
}
__device__ __forceinline__ void cp_commit() {
    asm volatile("cp.async.commit_group;" ::: "memory");
}
template <int N>
__device__ __forceinline__ void cp_wait() {
    asm volatile("cp.async.wait_group %0;" :: "n"(N) : "memory");
}
__device__ __forceinline__ void ldm_x4(uint32_t& r0, uint32_t& r1,
                                       uint32_t& r2, uint32_t& r3, uint32_t a) {
    asm volatile("ldmatrix.sync.aligned.m8n8.x4.shared.b16 {%0,%1,%2,%3}, [%4];"
                 : "=r"(r0), "=r"(r1), "=r"(r2), "=r"(r3) : "r"(a));
}
__device__ __forceinline__ void ldm_x4_t(uint32_t& r0, uint32_t& r1,
                                         uint32_t& r2, uint32_t& r3, uint32_t a) {
    asm volatile("ldmatrix.sync.aligned.m8n8.x4.trans.shared.b16 {%0,%1,%2,%3}, [%4];"
                 : "=r"(r0), "=r"(r1), "=r"(r2), "=r"(r3) : "r"(a));
}
__device__ __forceinline__ void mma_16816(float& c0, float& c1, float& c2, float& c3,
                                          uint32_t a0, uint32_t a1, uint32_t a2,
                                          uint32_t a3, uint32_t b0, uint32_t b1) {
    asm volatile(
        "mma.sync.aligned.m16n8k16.row.col.f32.bf16.bf16.f32 "
        "{%0,%1,%2,%3}, {%4,%5,%6,%7}, {%8,%9}, {%0,%1,%2,%3};"
        : "+f"(c0), "+f"(c1), "+f"(c2), "+f"(c3)
        : "r"(a0), "r"(a1), "r"(a2), "r"(a3), "r"(b0), "r"(b1));
}

// ---------------------------------------------------------------------------
// fp32 -> bf16 hi/lo convert kernels
// ---------------------------------------------------------------------------
__global__ __launch_bounds__(256) void convert_a_kernel(
    const float* __restrict__ p0, const float* __restrict__ p1,
    const float* __restrict__ p2)
{
    const int z = blockIdx.z;
    const float* src = (z == 0 ? p0 : z == 1 ? p1 : p2);
    const size_t base = (size_t)z * ((size_t)M * D);
    const size_t i = ((size_t)blockIdx.x * 256 + threadIdx.x) * 4;
    float4 v = *(const float4*)(src + i);

    __nv_bfloat16 hi[4], lo[4];
    float x[4] = {v.x, v.y, v.z, v.w};
    #pragma unroll
    for (int j = 0; j < 4; j++) {
        hi[j] = __float2bfloat16(x[j]);
        lo[j] = __float2bfloat16(x[j] - __bfloat162float(hi[j]));
    }
    *(uint2*)&g_Ahi[base + i] = *(uint2*)hi;
    *(uint2*)&g_Alo[base + i] = *(uint2*)lo;
}

// Transpose + split W: Wt[n][k] = W[k][n]
__global__ void convert_w_kernel(const float* __restrict__ w0,
                                 const float* __restrict__ w1,
                                 const float* __restrict__ w2,
                                 const float* __restrict__ w3)
{
    __shared__ float t[32][33];
    const int z = blockIdx.z;
    const float* W = z == 0 ? w0 : z == 1 ? w1 : z == 2 ? w2 : w3;
    const size_t base = (size_t)z * D * D;
    const int n0 = blockIdx.x * 32, k0 = blockIdx.y * 32;

    for (int i = threadIdx.y; i < 32; i += 8)
        t[i][threadIdx.x] = W[(size_t)(k0 + i) * D + n0 + threadIdx.x];
    __syncthreads();
    for (int i = threadIdx.y; i < 32; i += 8) {
        float x = t[threadIdx.x][i];
        __nv_bfloat16 h = __float2bfloat16(x);
        size_t o = base + (size_t)(n0 + i) * D + k0 + threadIdx.x;
        g_Bhi[o] = h;
        g_Blo[o] = __float2bfloat16(x - __bfloat162float(h));
    }
}

// ---------------------------------------------------------------------------
// bf16 mma.sync GEMM, 3-term split. CTA 128x128, BK=64, 8 warps (64x32).
// Per k16 step: load Ahi/Alo/Bhi/Blo fragments ONCE, then 3x16 MMAs.
// MODE 0: qkv projections -> bf16 hi/lo split to [B,H,S,DK]
// MODE 1: out projection (+bias, row-major fp32 out)
// ---------------------------------------------------------------------------
static constexpr int GBM = 128, GBN = 128, GBK = 64;
static constexpr int NC = D / GBK;                 // 16 chunks
static constexpr int RSTRIDE = 144;                // 128B data + 16B pad
static constexpr int TILE_B  = 128 * RSTRIDE;      // 18432
static constexpr int OA_HI = 0, OA_LO = TILE_B, OB_HI = 2 * TILE_B, OB_LO = 3 * TILE_B;
static constexpr int STG = 4 * TILE_B;             // 73728 per stage
static constexpr int GEMM_SMEM = 2 * STG;          // 147456

// load one 128x64 bf16 tile (128 rows x 128B = 1024 cp16 units) into smem
__device__ __forceinline__ void load_tile(const __nv_bfloat16* __restrict__ src,
                                          int row0, int k0, uint32_t sdst, int tid)
{
    #pragma unroll
    for (int i = 0; i < 4; i++) {
        int unit = tid + 256 * i;
        int r = unit >> 3, c = unit & 7;
        cp16(sdst + r * RSTRIDE + c * 16,
             src + (size_t)(row0 + r) * D + k0 + c * 8);
    }
}

template <int MODE>
__global__ __launch_bounds__(256, 1) void tc_gemm_kernel(
    float* __restrict__ out_param, const float* __restrict__ bias)
{
    extern __shared__ char smc[];
    const uint32_t sb = smem_u32(smc);
    const int tid = threadIdx.x;
    const int lane = tid & 31, wid = tid >> 5;
    const int z = blockIdx.z;
    const int bm = blockIdx.y * GBM;
    const int bn = blockIdx.x * GBN;

    const __nv_bfloat16* Ahi = g_Ahi + (MODE == 0 ? (size_t)z * M * D : 0);
    const __nv_bfloat16* Alo = g_Alo + (MODE == 0 ? (size_t)z * M * D : 0);
    const __nv_bfloat16* Bhi = g_Bhi + (MODE == 0 ? (size_t)z * D * D : (size_t)3 * D * D);
    const __nv_bfloat16* Blo = g_Blo + (MODE == 0 ? (size_t)z * D * D : (size_t)3 * D * D);

    const int m_warp = (wid & 1) * 64;
    const int n_warp = (wid >> 1) * 32;

    const uint32_t a_lane = (uint32_t)((lane & 15) * RSTRIDE + ((lane >> 4) & 1) * 16);
    const uint32_t b_lane = (uint32_t)((((lane >> 4) & 1) * 8 + (lane & 7)) * RSTRIDE
                                       + ((lane >> 3) & 1) * 16);

    float acc[4][4][4];
    #pragma unroll
    for (int i = 0; i < 4; i++)
        #pragma unroll
        for (int j = 0; j < 4; j++)
            #pragma unroll
            for (int e = 0; e < 4; e++) acc[i][j][e] = 0.f;

    load_tile(Ahi, bm, 0, sb + OA_HI, tid);
    load_tile(Alo, bm, 0, sb + OA_LO, tid);
    load_tile(Bhi, bn, 0, sb + OB_HI, tid);
    load_tile(Blo, bn, 0, sb + OB_LO, tid);
    cp_commit();

    for (int c = 0; c < NC; c++) {
        const int s = c & 1;
        if (c + 1 < NC) {
            const uint32_t nb = sb + (s ^ 1) * STG;
            const int k0 = (c + 1) * GBK;
            load_tile(Ahi, bm, k0, nb + OA_HI, tid);
            load_tile(Alo, bm, k0, nb + OA_LO, tid);
            load_tile(Bhi, bn, k0, nb + OB_HI, tid);
            load_tile(Blo, bn, k0, nb + OB_LO, tid);
            cp_commit();
            cp_wait<1>();
        } else {
            cp_wait<0>();
        }
        __syncthreads();

        const uint32_t stg = sb + s * STG;
        #pragma unroll
        for (int t = 0; t < 4; t++) {
            // load all fragments for this k16 step exactly once
            uint32_t ah[4][4], al[4][4];
            #pragma unroll
            for (int i = 0; i < 4; i++) {
                const uint32_t ro = (uint32_t)((m_warp + i * 16) * RSTRIDE + t * 32) + a_lane;
                ldm_x4(ah[i][0], ah[i][1], ah[i][2], ah[i][3], stg + OA_HI + ro);
                ldm_x4(al[i][0], al[i][1], al[i][2], al[i][3], stg + OA_LO + ro);
            }
            uint32_t bh[8], bl[8];
            #pragma unroll
            for (int p = 0; p < 2; p++) {
                const uint32_t ro = (uint32_t)((n_warp + p * 16) * RSTRIDE + t * 32) + b_lane;
                ldm_x4(bh[p * 4 + 0], bh[p * 4 + 1], bh[p * 4 + 2], bh[p * 4 + 3],
                       stg + OB_HI + ro);
                ldm_x4(bl[p * 4 + 0], bl[p * 4 + 1], bl[p * 4 + 2], bl[p * 4 + 3],
                       stg + OB_LO + ro);
            }
            #pragma unroll
            for (int i = 0; i < 4; i++)
                #pragma unroll
                for (int j = 0; j < 4; j++) {
                    const int bi = (j >> 1) * 4 + (j & 1) * 2;
                    mma_16816(acc[i][j][0], acc[i][j][1], acc[i][j][2], acc[i][j][3],
                              ah[i][0], ah[i][1], ah[i][2], ah[i][3],
                              bh[bi], bh[bi + 1]);
                    mma_16816(acc[i][j][0], acc[i][j][1], acc[i][j][2], acc[i][j][3],
                              ah[i][0], ah[i][1], ah[i][2], ah[i][3],
                              bl[bi], bl[bi + 1]);
                    mma_16816(acc[i][j][0], acc[i][j][1], acc[i][j][2], acc[i][j][3],
                              al[i][0], al[i][1], al[i][2], al[i][3],
                              bh[bi], bh[bi + 1]);
                }
        }
        __syncthreads();
    }

    // Epilogue
    const int g = lane >> 2, tq = lane & 3;
    #pragma unroll
    for (int i = 0; i < 4; i++) {
        #pragma unroll
        for (int j = 0; j < 4; j++) {
            const int n = bn + n_warp + j * 8 + tq * 2;
            #pragma unroll
            for (int half = 0; half < 2; half++) {
                const int m = bm + m_warp + i * 16 + g + half * 8;
                float2 v = make_float2(acc[i][j][half * 2], acc[i][j][half * 2 + 1]);
                if (MODE == 0) {
                    __nv_bfloat16* dhi = z == 0 ? g_qhi : z == 1 ? g_khi : g_vhi;
                    __nv_bfloat16* dlo = z == 0 ? g_qlo : z == 1 ? g_klo : g_vlo;
                    const int bb = m >> 11, ss = m & (S - 1);
                    const int h = n >> 6, d0 = n & (DK - 1);
                    const size_t idx = ((size_t)(bb * H + h) * S + ss) * DK + d0;
                    __nv_bfloat162 hv = __float22bfloat162_rn(v);
                    float2 hf = __bfloat1622float2(hv);
                    __nv_bfloat162 lv = __float22bfloat162_rn(
                        make_float2(v.x - hf.x, v.y - hf.y));
                    *(__nv_bfloat162*)(dhi + idx) = hv;
                    *(__nv_bfloat162*)(dlo + idx) = lv;
                } else {
                    float2 bv = *(const float2*)(bias + n);
                    v.x += bv.x; v.y += bv.y;
                    *(float2*)(out_param + (size_t)m * D + n) = v;
                }
            }
        }
    }
}

// ---------------------------------------------------------------------------
// Tensor-core flash attention (FA2-style, bf16 mma.sync, 3-term split).
// CTA: 256 threads = 8 warps, 128 Q rows (m16 per warp), 64-key tiles.
// Epilogue writes bf16 hi/lo into g_Ahi/g_Alo slot 0 ([M, D] row-major),
// feeding the out-projection GEMM directly (no fp32 round-trip).
// ---------------------------------------------------------------------------
static constexpr int RST = 144;                 // smem row stride (bytes)
static constexpr int KV_TERM = 64 * RST;        // 9216 per tile-term
static constexpr int KV_STG  = 4 * KV_TERM;     // khi,klo,vhi,vlo = 36864
static constexpr int ATTN_SMEM = 2 * KV_STG;    // 73728

__global__ __launch_bounds__(256, 1) void flash_attn_tc()
{
    extern __shared__ char smc[];
    const uint32_t sb = smem_u32(smc);
    const int tid = threadIdx.x, lane = tid & 31, wid = tid >> 5;
    const int qb = (int)gridDim.x - 1 - (int)blockIdx.x;   // reversed: heavy first
    const int bh = blockIdx.y;
    const int ntiles = 2 * qb + 2;
    const size_t bho = (size_t)bh * S * DK;

    const __nv_bfloat16* qh_g = g_qhi + bho + (size_t)qb * 128 * DK;
    const __nv_bfloat16* ql_g = g_qlo + bho + (size_t)qb * 128 * DK;
    const __nv_bfloat16* kh_g = g_khi + bho;
    const __nv_bfloat16* kl_g = g_klo + bho;
    const __nv_bfloat16* vh_g = g_vhi + bho;
    const __nv_bfloat16* vl_g = g_vlo + bho;

    // ---- stage Q tile (128x64 hi/lo) through smem, distribute to registers ----
    #pragma unroll
    for (int i = 0; i < 4; i++) {
        int u = tid + 256 * i, r = u >> 3, c = u & 7;
        cp16(sb + r * RST + c * 16, qh_g + r * DK + c * 8);
        cp16(sb + 2 * KV_TERM + r * RST + c * 16, ql_g + r * DK + c * 8);
    }
    cp_commit(); cp_wait<0>(); __syncthreads();

    const uint32_t a_lane = (uint32_t)((lane & 15) * RST + (lane >> 4) * 16);
    uint32_t qh[4][4], ql[4][4];
    #pragma unroll
    for (int kt = 0; kt < 4; kt++) {
        ldm_x4(qh[kt][0], qh[kt][1], qh[kt][2], qh[kt][3],
               sb + (uint32_t)(wid * 16) * RST + kt * 32 + a_lane);
        ldm_x4(ql[kt][0], ql[kt][1], ql[kt][2], ql[kt][3],
               sb + 2 * KV_TERM + (uint32_t)(wid * 16) * RST + kt * 32 + a_lane);
    }
    __syncthreads();

    const uint32_t b_lane = (uint32_t)(((((lane >> 4) & 1) * 8) + (lane & 7)) * RST
                                       + ((lane >> 3) & 1) * 16);
    const uint32_t v_lane = (uint32_t)(((((lane >> 3) & 1) * 8) + (lane & 7)) * RST
                                       + (lane >> 4) * 16);

    auto load_kv = [&](int nt, uint32_t dstb) {
        const int kb0 = nt * 64;
        #pragma unroll
        for (int i = 0; i < 2; i++) {
            int u = tid + 256 * i, r = u >> 3, c = u & 7;
            size_t g = (size_t)(kb0 + r) * DK + c * 8;
            uint32_t so = dstb + (uint32_t)(r * RST + c * 16);
            cp16(so + 0 * KV_TERM, kh_g + g);
            cp16(so + 1 * KV_TERM, kl_g + g);
            cp16(so + 2 * KV_TERM, vh_g + g);
            cp16(so + 3 * KV_TERM, vl_g + g);
        }
    };

    float o[8][4];
    #pragma unroll
    for (int j = 0; j < 8; j++)
        #pragma unroll
        for (int e = 0; e < 4; e++) o[j][e] = 0.f;
    float row_m[2] = {-1e30f, -1e30f}, row_l[2] = {0.f, 0.f};
    const int m0w = qb * 128 + wid * 16;

    load_kv(0, sb);
    cp_commit();

    for (int nt = 0; nt < ntiles; nt++) {
        if (nt + 1 < ntiles) {
            load_kv(nt + 1, sb + (uint32_t)((nt + 1) & 1) * KV_STG);
            cp_commit();
            cp_wait<1>();
        } else {
            cp_wait<0>();
        }
        __syncthreads();

        const int kbase = nt * 64;
        if (kbase <= m0w + 15) {                  // warp has unmasked work
            const uint32_t stg = sb + (uint32_t)(nt & 1) * KV_STG;

            // ---- S = Q K^T, 3 terms ----
            float sc[8][4];
            #pragma unroll
            for (int j = 0; j < 8; j++)
                #pragma unroll
                for (int e = 0; e < 4; e++) sc[j][e] = 0.f;

            #pragma unroll
            for (int kt = 0; kt < 4; kt++) {
                #pragma unroll
                for (int nb = 0; nb < 4; nb++) {
                    uint32_t bk[4];
                    const uint32_t tb = (uint32_t)(nb * 16) * RST + kt * 32;
                    ldm_x4(bk[0], bk[1], bk[2], bk[3], stg + tb + b_lane);  // khi
                    #pragma unroll
                    for (int j2 = 0; j2 < 2; j2++) {
                        const int j = nb * 2 + j2;
                        mma_16816(sc[j][0], sc[j][1], sc[j][2], sc[j][3],
                                  qh[kt][0], qh[kt][1], qh[kt][2], qh[kt][3],
                                  bk[j2 * 2], bk[j2 * 2 + 1]);
                        mma_16816(sc[j][0], sc[j][1], sc[j][2], sc[j][3],
                                  ql[kt][0], ql[kt][1], ql[kt][2], ql[kt][3],
                                  bk[j2 * 2], bk[j2 * 2 + 1]);
                    }
                    ldm_x4(bk[0], bk[1], bk[2], bk[3],
                           stg + KV_TERM + tb + b_lane);                    // klo
                    #pragma unroll
                    for (int j2 = 0; j2 < 2; j2++) {
                        const int j = nb * 2 + j2;
                        mma_16816(sc[j][0], sc[j][1], sc[j][2], sc[j][3],
                                  qh[kt][0], qh[kt][1], qh[kt][2], qh[kt][3],
                                  bk[j2 * 2], bk[j2 * 2 + 1]);
                    }
                }
            }

            // scale + causal mask
            const bool needm = (kbase + 63) > m0w;
            #pragma unroll
            for (int j = 0; j < 8; j++)
                #pragma unroll
                for (int e = 0; e < 4; e++) {
                    float x = sc[j][e] * 0.125f;
                    if (needm) {
                        const int key = kbase + j * 8 + (lane & 3) * 2 + (e & 1);
                        const int row = m0w + (lane >> 2) + (e >> 1) * 8;
                        if (key > row) x = -1e30f;
                    }
                    sc[j][e] = x;
                }

            // ---- online softmax (per row-half) ----
            #pragma unroll
            for (int h2 = 0; h2 < 2; h2++) {
                float mx = -1e30f;
                #pragma unroll
                for (int j = 0; j < 8; j++)
                    mx = fmaxf(mx, fmaxf(sc[j][h2 * 2], sc[j][h2 * 2 + 1]));
                mx = fmaxf(mx, __shfl_xor_sync(0xffffffffu, mx, 1));
                mx = fmaxf(mx, __shfl_xor_sync(0xffffffffu, mx, 2));
                const float mn = fmaxf(row_m[h2], mx);
                const float corr = __expf(row_m[h2] - mn);
                float sum = 0.f;
                #pragma unroll
                for (int j = 0; j < 8; j++) {
                    float p0 = __expf(sc[j][h2 * 2] - mn);
                    float p1 = __expf(sc[j][h2 * 2 + 1] - mn);
                    sc[j][h2 * 2] = p0; sc[j][h2 * 2 + 1] = p1;
                    sum += p0 + p1;
                }
                sum += __shfl_xor_sync(0xffffffffu, sum, 1);
                sum += __shfl_xor_sync(0xffffffffu, sum, 2);
                row_l[h2] = row_l[h2] * corr + sum;
                row_m[h2] = mn;
                #pragma unroll
                for (int j = 0; j < 8; j++) {
                    o[j][h2 * 2] *= corr;
                    o[j][h2 * 2 + 1] *= corr;
                }
            }

            // ---- pack P into bf16 hi/lo A-fragments (register-only) ----
            uint32_t pHi[8][2], pLo[8][2];
            #pragma unroll
            for (int j = 0; j < 8; j++)
                #pragma unroll
                for (int pr = 0; pr < 2; pr++) {
                    float p0 = sc[j][pr * 2], p1 = sc[j][pr * 2 + 1];
                    __nv_bfloat162 hv = __float22bfloat162_rn(make_float2(p0, p1));
                    float2 hf = __bfloat1622float2(hv);
                    __nv_bfloat162 lv = __float22bfloat162_rn(
                        make_float2(p0 - hf.x, p1 - hf.y));
                    pHi[j][pr] = *(uint32_t*)&hv;
                    pLo[j][pr] = *(uint32_t*)&lv;
                }

            // ---- O += P V, 3 terms (V^T fragments via ldmatrix.trans) ----
            #pragma unroll
            for (int kt = 0; kt < 4; kt++) {
                const uint32_t ah0 = pHi[2 * kt][0], ah1 = pHi[2 * kt][1];
                const uint32_t ah2 = pHi[2 * kt + 1][0], ah3 = pHi[2 * kt + 1][1];
                const uint32_t al0 = pLo[2 * kt][0], al1 = pLo[2 * kt][1];
                const uint32_t al2 = pLo[2 * kt + 1][0], al3 = pLo[2 * kt + 1][1];
                #pragma unroll
                for (int nb = 0; nb < 4; nb++) {
                    uint32_t bv[4];
                    const uint32_t tb = (uint32_t)(kt * 16) * RST + nb * 32;
                    ldm_x4_t(bv[0], bv[1], bv[2], bv[3],
                             stg + 2 * KV_TERM + tb + v_lane);               // vhi
                    #pragma unroll
                    for (int j2 = 0; j2 < 2; j2++) {
                        const int j = nb * 2 + j2;
                        mma_16816(o[j][0], o[j][1], o[j][2], o[j][3],
                                  ah0, ah1, ah2, ah3, bv[j2 * 2], bv[j2 * 2 + 1]);
                        mma_16816(o[j][0], o[j][1], o[j][2], o[j][3],
                                  al0, al1, al2, al3, bv[j2 * 2], bv[j2 * 2 + 1]);
                    }
                    ldm_x4_t(bv[0], bv[1], bv[2], bv[3],
                             stg + 3 * KV_TERM + tb + v_lane);               // vlo
                    #pragma unroll
                    for (int j2 = 0; j2 < 2; j2++) {
                        const int j = nb * 2 + j2;
                        mma_16816(o[j][0], o[j][1], o[j][2], o[j][3],
                                  ah0, ah1, ah2, ah3, bv[j2 * 2], bv[j2 * 2 + 1]);
                    }
                }
            }
        }
        __syncthreads();
    }

    // ---- epilogue: normalize + bf16 hi/lo split straight into out-proj A ----
    const int b = bh >> 4, head = bh & (H - 1);
    #pragma unroll
    for (int h2 = 0; h2 < 2; h2++) {
        const float inv = 1.0f / row_l[h2];
        const int row = m0w + (lane >> 2) + h2 * 8;
        #pragma unroll
        for (int j = 0; j < 8; j++) {
            const int col = head * DK + j * 8 + (lane & 3) * 2;
            const size_t idx = (size_t)(b * S + row) * D + col;
            float2 v = make_float2(o[j][h2 * 2] * inv, o[j][h2 * 2 + 1] * inv);
            __nv_bfloat162 hv = __float22bfloat162_rn(v);
            float2 hf = __bfloat1622float2(hv);
            __nv_bfloat162 lv = __float22bfloat162_rn(
                make_float2(v.x - hf.x, v.y - hf.y));
            *(__nv_bfloat162*)(g_Ahi + idx) = hv;
            *(__nv_bfloat162*)(g_Alo + idx) = lv;
        }
    }
}

// ---------------------------------------------------------------------------
extern "C" void kernel_launch(void* const* d_in, const int* in_sizes, int n_in,
                              void* d_out, int out_size)
{
    const float* Q  = (const float*)d_in[0];
    const float* K  = (const float*)d_in[1];
    const float* V  = (const float*)d_in[2];
    const float* Wq = (const float*)d_in[3];
    const float* Wk = (const float*)d_in[4];
    const float* Wv = (const float*)d_in[5];
    const float* Wo = (const float*)d_in[6];
    const float* bo = (const float*)d_in[7];
    float* out = (float*)d_out;

    (void)in_sizes; (void)n_in; (void)out_size;

    cudaFuncSetAttribute(tc_gemm_kernel<0>,
                         cudaFuncAttributeMaxDynamicSharedMemorySize, GEMM_SMEM);
    cudaFuncSetAttribute(tc_gemm_kernel<1>,
                         cudaFuncAttributeMaxDynamicSharedMemorySize, GEMM_SMEM);
    cudaFuncSetAttribute(flash_attn_tc,
                         cudaFuncAttributeMaxDynamicSharedMemorySize, ATTN_SMEM);

    // fp32 -> bf16 hi/lo conversions of inputs + weights
    convert_a_kernel<<<dim3(M * D / (256 * 4), 1, 3), 256>>>(Q, K, V);
    convert_w_kernel<<<dim3(D / 32, D / 32, 4), dim3(32, 8)>>>(Wq, Wk, Wv, Wo);

    // Q/K/V projections (HMMA) -> bf16 hi/lo split q,k,v
    tc_gemm_kernel<0><<<dim3(D / GBN, M / GBM, 3), 256, GEMM_SMEM>>>(nullptr, nullptr);

    // Tensor-core flash attention (writes out-proj A operand directly)
    flash_attn_tc<<<dim3(S / 128, B * H), 256, ATTN_SMEM>>>();

    // Output projection (+bias)
    tc_gemm_kernel<1><<<dim3(D / GBN, M / GBM, 1), 256, GEMM_SMEM>>>(out, bo);
}